// round 11
// baseline (speedup 1.0000x reference)
#include <cuda_runtime.h>
#include <cuda_fp16.h>

#define IN_DIM   8192
#define OUT_DIM  16384
#define B_ROWS   2048

constexpr int THREADS      = 1024;
constexpr int SLAB_ROWS    = 8;                        // fp16 rows per smem slot
constexpr int PHASES       = 2;                        // row-slabs per CTA
constexpr int ROWS_PER_CTA = SLAB_ROWS * PHASES;       // 16
constexpr int GROUPS       = OUT_DIM / (THREADS * 4);  // 4 col-groups of 4
constexpr int SLAB_BYTES   = IN_DIM * SLAB_ROWS * 2;   // 128 KB
constexpr int IDX_BYTES    = OUT_DIM * 4;              // 64 KB
constexpr int SMEM_BYTES   = SLAB_BYTES + IDX_BYTES;   // 192 KB

// 16-byte slot holding 8 fp16 batch rows of one input column.
struct alignas(16) H8 { half2 h[4]; };
// 8-byte fp16 coefficient quad: {c1, ca}, {cb, cab}.
struct alignas(8) CF4 { __half2 p01; __half2 p23; };

// Precomputed per-output-column data.
__device__ CF4      g_cf [OUT_DIM];   // out = c1 + ca*a + cb*b + cab*ab
__device__ unsigned g_idx[OUT_DIM];   // idx_a | (idx_b << 16)

// ---------------------------------------------------------------------------
// Kernel 1: softmax(weights) -> affine coefficients (fp16); pack idx pairs.
// ---------------------------------------------------------------------------
__global__ void coef_kernel(const float* __restrict__ w,
                            const int*   __restrict__ idx_a,
                            const int*   __restrict__ idx_b)
{
    int o = blockIdx.x * blockDim.x + threadIdx.x;
    if (o >= OUT_DIM) return;

    const float4* w4 = reinterpret_cast<const float4*>(w + (size_t)o * 16);
    float v[16];
#pragma unroll
    for (int q = 0; q < 4; q++) {
        float4 t = w4[q];
        v[4 * q + 0] = t.x; v[4 * q + 1] = t.y;
        v[4 * q + 2] = t.z; v[4 * q + 3] = t.w;
    }

    float m = -1e30f;
#pragma unroll
    for (int i = 0; i < 16; i++) m = fmaxf(m, v[i]);
    float s = 0.0f;
#pragma unroll
    for (int i = 0; i < 16; i++) {
        v[i] = __expf(v[i] - m);
        s += v[i];
    }
    float inv = 1.0f / s;
#pragma unroll
    for (int i = 0; i < 16; i++) v[i] *= inv;

    // Gate table (difflogic order); gate 0 == 0 so v[0] unused.
    float c1  = v[8] + v[9] + v[10] + v[11] + v[12] + v[13] + v[14] + v[15];
    float ca  = v[2] + v[3] + v[6] + v[7] - v[8] - v[9] - v[12] - v[13];
    float cb  = v[4] + v[5] + v[6] + v[7] - v[8] - v[9] - v[10] - v[11];
    float cab = v[1] - v[2] - v[4] - 2.0f * v[6] - v[7]
              + v[8] + 2.0f * v[9] + v[11] + v[13] - v[14];

    CF4 cf;
    cf.p01 = __floats2half2_rn(c1, ca);
    cf.p23 = __floats2half2_rn(cb, cab);
    g_cf[o]  = cf;
    g_idx[o] = (unsigned)idx_a[o] | ((unsigned)idx_b[o] << 16);
}

// Evaluate one column's pair of rows from packed half2 inputs.
__device__ __forceinline__ void eval2(float2 c01, float2 c23, half2 ah, half2 bh,
                                      float& lo, float& hi)
{
    float2 af = __half22float2(ah);
    float2 bf = __half22float2(bh);
    lo = fmaf(c23.y, af.x * bf.x, fmaf(c23.x, bf.x, fmaf(c01.y, af.x, c01.x)));
    hi = fmaf(c23.y, af.y * bf.y, fmaf(c23.x, bf.y, fmaf(c01.y, af.y, c01.x)));
}

// ---------------------------------------------------------------------------
// Kernel 2: one CTA = 16 batch rows x all 16384 cols, as two 8-row phases.
// Each thread handles 4 consecutive columns -> float4 output stores.
// ---------------------------------------------------------------------------
__global__ __launch_bounds__(THREADS, 1)
void logic_kernel(const float* __restrict__ x,
                  float*       __restrict__ out)
{
    extern __shared__ char smem[];
    H8*       sx   = reinterpret_cast<H8*>(smem);                     // [IN_DIM]
    unsigned* sidx = reinterpret_cast<unsigned*>(smem + SLAB_BYTES);  // [OUT_DIM]

    const int lane = threadIdx.x & 31;
    const int warp = threadIdx.x >> 5;
    constexpr int NWARPS = THREADS / 32;

    // Load packed idx into smem once (coalesced uint4).
    {
        const uint4* gi = reinterpret_cast<const uint4*>(g_idx);
        uint4*       si = reinterpret_cast<uint4*>(sidx);
#pragma unroll
        for (int i = threadIdx.x; i < OUT_DIM / 4; i += THREADS)
            si[i] = gi[i];
    }

#pragma unroll
    for (int ph = 0; ph < PHASES; ph++) {
        const int row0 = blockIdx.x * ROWS_PER_CTA + ph * SLAB_ROWS;

        __syncthreads();  // previous phase's smem reads done (and idx ready)

        // Transposed fp16 staging: per 32-column group, 8 coalesced row loads,
        // convert to half, one contiguous STS.128 per lane (conflict-free).
        const float* xb = x + (size_t)row0 * IN_DIM;
#pragma unroll
        for (int g = warp; g < IN_DIM / 32; g += NWARPS) {
            int col = g * 32 + lane;
            H8 v;
#pragma unroll
            for (int p = 0; p < 4; p++) {
                v.h[p] = make_half2(__float2half_rn(xb[(size_t)(2 * p + 0) * IN_DIM + col]),
                                    __float2half_rn(xb[(size_t)(2 * p + 1) * IN_DIM + col]));
            }
            sx[col] = v;
        }
        __syncthreads();

#pragma unroll
        for (int gq = 0; gq < GROUPS; gq++) {
            const int col = (gq * THREADS + threadIdx.x) * 4;

            // 4 packed idx pairs in one LDS.128.
            const uint4 id4 = *reinterpret_cast<const uint4*>(sidx + col);

            // 8 gather LDS.128 issued together (8 rows x {a,b} x 4 cols).
            const H8 a0 = sx[id4.x & 0xFFFFu], b0 = sx[id4.x >> 16];
            const H8 a1 = sx[id4.y & 0xFFFFu], b1 = sx[id4.y >> 16];
            const H8 a2 = sx[id4.z & 0xFFFFu], b2 = sx[id4.z >> 16];
            const H8 a3 = sx[id4.w & 0xFFFFu], b3 = sx[id4.w >> 16];

            // 4 columns of fp16 coefs via two LDG.128.
            const float4* cfp = reinterpret_cast<const float4*>(g_cf + col);
            const float4 cfa = cfp[0];   // cols 0,1
            const float4 cfb = cfp[1];   // cols 2,3
            const float2 c01_0 = __half22float2(*(const __half2*)&cfa.x);
            const float2 c23_0 = __half22float2(*(const __half2*)&cfa.y);
            const float2 c01_1 = __half22float2(*(const __half2*)&cfa.z);
            const float2 c23_1 = __half22float2(*(const __half2*)&cfa.w);
            const float2 c01_2 = __half22float2(*(const __half2*)&cfb.x);
            const float2 c23_2 = __half22float2(*(const __half2*)&cfb.y);
            const float2 c01_3 = __half22float2(*(const __half2*)&cfb.z);
            const float2 c23_3 = __half22float2(*(const __half2*)&cfb.w);

            float* o0 = out + (size_t)row0 * OUT_DIM + col;
#pragma unroll
            for (int p = 0; p < 4; p++) {
                float4 lo, hi;
                eval2(c01_0, c23_0, a0.h[p], b0.h[p], lo.x, hi.x);
                eval2(c01_1, c23_1, a1.h[p], b1.h[p], lo.y, hi.y);
                eval2(c01_2, c23_2, a2.h[p], b2.h[p], lo.z, hi.z);
                eval2(c01_3, c23_3, a3.h[p], b3.h[p], lo.w, hi.w);
                __stcs(reinterpret_cast<float4*>(o0 + (size_t)(2 * p + 0) * OUT_DIM), lo);
                __stcs(reinterpret_cast<float4*>(o0 + (size_t)(2 * p + 1) * OUT_DIM), hi);
            }
        }
    }
}

// ---------------------------------------------------------------------------
// Launch
// ---------------------------------------------------------------------------
extern "C" void kernel_launch(void* const* d_in, const int* in_sizes, int n_in,
                              void* d_out, int out_size)
{
    const float* x  = (const float*)d_in[0];   // [2048, 8192] f32
    const float* w  = (const float*)d_in[1];   // [16384, 16]  f32
    const int*   ia = (const int*)d_in[2];     // [16384] i32
    const int*   ib = (const int*)d_in[3];     // [16384] i32
    float*       out = (float*)d_out;          // [2048, 16384] f32

    coef_kernel<<<OUT_DIM / 128, 128>>>(w, ia, ib);

    cudaFuncSetAttribute(logic_kernel,
                         cudaFuncAttributeMaxDynamicSharedMemorySize, SMEM_BYTES);

    logic_kernel<<<B_ROWS / ROWS_PER_CTA, THREADS, SMEM_BYTES>>>(x, out);  // 128 CTAs
}

// round 12
// speedup vs baseline: 1.0513x; 1.0513x over previous
#include <cuda_runtime.h>
#include <cuda_fp16.h>

#define IN_DIM   8192
#define OUT_DIM  16384
#define B_ROWS   2048

constexpr int THREADS      = 1024;
constexpr int SLAB_ROWS    = 8;                        // fp16 rows per smem slot
constexpr int PHASES       = 2;                        // row-slabs per CTA
constexpr int ROWS_PER_CTA = SLAB_ROWS * PHASES;       // 16
constexpr int GROUPS       = OUT_DIM / (THREADS * 2);  // 8 groups of 2 cols
constexpr int SLAB_BYTES   = IN_DIM * SLAB_ROWS * 2;   // 128 KB
constexpr int IDX_BYTES    = OUT_DIM * 4;              // 64 KB
constexpr int SMEM_BYTES   = SLAB_BYTES + IDX_BYTES;   // 192 KB

// 16-byte slot holding 8 fp16 batch rows of one input column.
struct alignas(16) H8 { half2 h[4]; };
// 8-byte fp16 coefficient quad: {c1, ca}, {cb, cab}.
struct alignas(8) CF4 { __half2 p01; __half2 p23; };

// Precomputed per-output-column data.
__device__ CF4      g_cf [OUT_DIM];   // out = c1 + ca*a + cb*b + cab*ab
__device__ unsigned g_idx[OUT_DIM];   // idx_a | (idx_b << 16)

// ---------------------------------------------------------------------------
// Kernel 1: softmax(weights) -> affine coefficients (fp16); pack idx pairs.
// ---------------------------------------------------------------------------
__global__ void coef_kernel(const float* __restrict__ w,
                            const int*   __restrict__ idx_a,
                            const int*   __restrict__ idx_b)
{
    int o = blockIdx.x * blockDim.x + threadIdx.x;
    if (o >= OUT_DIM) return;

    const float4* w4 = reinterpret_cast<const float4*>(w + (size_t)o * 16);
    float v[16];
#pragma unroll
    for (int q = 0; q < 4; q++) {
        float4 t = w4[q];
        v[4 * q + 0] = t.x; v[4 * q + 1] = t.y;
        v[4 * q + 2] = t.z; v[4 * q + 3] = t.w;
    }

    float m = -1e30f;
#pragma unroll
    for (int i = 0; i < 16; i++) m = fmaxf(m, v[i]);
    float s = 0.0f;
#pragma unroll
    for (int i = 0; i < 16; i++) {
        v[i] = __expf(v[i] - m);
        s += v[i];
    }
    float inv = 1.0f / s;
#pragma unroll
    for (int i = 0; i < 16; i++) v[i] *= inv;

    // Gate table (difflogic order); gate 0 == 0 so v[0] unused.
    float c1  = v[8] + v[9] + v[10] + v[11] + v[12] + v[13] + v[14] + v[15];
    float ca  = v[2] + v[3] + v[6] + v[7] - v[8] - v[9] - v[12] - v[13];
    float cb  = v[4] + v[5] + v[6] + v[7] - v[8] - v[9] - v[10] - v[11];
    float cab = v[1] - v[2] - v[4] - 2.0f * v[6] - v[7]
              + v[8] + 2.0f * v[9] + v[11] + v[13] - v[14];

    CF4 cf;
    cf.p01 = __floats2half2_rn(c1, ca);
    cf.p23 = __floats2half2_rn(cb, cab);
    g_cf[o]  = cf;
    g_idx[o] = (unsigned)idx_a[o] | ((unsigned)idx_b[o] << 16);
}

// Evaluate one column's pair of rows from packed half2 inputs.
__device__ __forceinline__ void eval2(float2 c01, float2 c23, half2 ah, half2 bh,
                                      float& lo, float& hi)
{
    float2 af = __half22float2(ah);
    float2 bf = __half22float2(bh);
    lo = fmaf(c23.y, af.x * bf.x, fmaf(c23.x, bf.x, fmaf(c01.y, af.x, c01.x)));
    hi = fmaf(c23.y, af.y * bf.y, fmaf(c23.x, bf.y, fmaf(c01.y, af.y, c01.x)));
}

// ---------------------------------------------------------------------------
// Kernel 2: one CTA = 16 batch rows x all 16384 cols, as two 8-row phases.
// Each thread handles 2 consecutive columns -> float2 output stores.
// ---------------------------------------------------------------------------
__global__ __launch_bounds__(THREADS, 1)
void logic_kernel(const float* __restrict__ x,
                  float*       __restrict__ out)
{
    extern __shared__ char smem[];
    H8*       sx   = reinterpret_cast<H8*>(smem);                     // [IN_DIM]
    unsigned* sidx = reinterpret_cast<unsigned*>(smem + SLAB_BYTES);  // [OUT_DIM]

    const int lane = threadIdx.x & 31;
    const int warp = threadIdx.x >> 5;
    constexpr int NWARPS = THREADS / 32;

    // Load packed idx into smem once (coalesced uint4).
    {
        const uint4* gi = reinterpret_cast<const uint4*>(g_idx);
        uint4*       si = reinterpret_cast<uint4*>(sidx);
#pragma unroll
        for (int i = threadIdx.x; i < OUT_DIM / 4; i += THREADS)
            si[i] = gi[i];
    }

#pragma unroll
    for (int ph = 0; ph < PHASES; ph++) {
        const int row0 = blockIdx.x * ROWS_PER_CTA + ph * SLAB_ROWS;

        __syncthreads();  // previous phase's smem reads done (and idx ready)

        // Transposed fp16 staging: per 32-column group, 8 coalesced row loads,
        // convert to half, one contiguous STS.128 per lane (conflict-free).
        const float* xb = x + (size_t)row0 * IN_DIM;
#pragma unroll
        for (int g = warp; g < IN_DIM / 32; g += NWARPS) {
            int col = g * 32 + lane;
            H8 v;
#pragma unroll
            for (int p = 0; p < 4; p++) {
                v.h[p] = make_half2(__float2half_rn(xb[(size_t)(2 * p + 0) * IN_DIM + col]),
                                    __float2half_rn(xb[(size_t)(2 * p + 1) * IN_DIM + col]));
            }
            sx[col] = v;
        }
        __syncthreads();

#pragma unroll
        for (int gq = 0; gq < GROUPS; gq++) {
            const int col = (gq * THREADS + threadIdx.x) * 2;

            // 2 packed idx pairs in one LDS.64.
            const uint2 id2 = *reinterpret_cast<const uint2*>(sidx + col);

            // 4 gather LDS.128 (8 rows x {a,b} x 2 cols).
            const H8 a0 = sx[id2.x & 0xFFFFu], b0 = sx[id2.x >> 16];
            const H8 a1 = sx[id2.y & 0xFFFFu], b1 = sx[id2.y >> 16];

            // 2 columns of fp16 coefs via one LDG.128.
            const float4 cfa = *reinterpret_cast<const float4*>(g_cf + col);
            const float2 c01_0 = __half22float2(*(const __half2*)&cfa.x);
            const float2 c23_0 = __half22float2(*(const __half2*)&cfa.y);
            const float2 c01_1 = __half22float2(*(const __half2*)&cfa.z);
            const float2 c23_1 = __half22float2(*(const __half2*)&cfa.w);

            float* o0 = out + (size_t)row0 * OUT_DIM + col;
#pragma unroll
            for (int p = 0; p < 4; p++) {
                float2 lo, hi;
                eval2(c01_0, c23_0, a0.h[p], b0.h[p], lo.x, hi.x);
                eval2(c01_1, c23_1, a1.h[p], b1.h[p], lo.y, hi.y);
                __stcs(reinterpret_cast<float2*>(o0 + (size_t)(2 * p + 0) * OUT_DIM), lo);
                __stcs(reinterpret_cast<float2*>(o0 + (size_t)(2 * p + 1) * OUT_DIM), hi);
            }
        }
    }
}

// ---------------------------------------------------------------------------
// Launch
// ---------------------------------------------------------------------------
extern "C" void kernel_launch(void* const* d_in, const int* in_sizes, int n_in,
                              void* d_out, int out_size)
{
    const float* x  = (const float*)d_in[0];   // [2048, 8192] f32
    const float* w  = (const float*)d_in[1];   // [16384, 16]  f32
    const int*   ia = (const int*)d_in[2];     // [16384] i32
    const int*   ib = (const int*)d_in[3];     // [16384] i32
    float*       out = (float*)d_out;          // [2048, 16384] f32

    coef_kernel<<<OUT_DIM / 128, 128>>>(w, ia, ib);

    cudaFuncSetAttribute(logic_kernel,
                         cudaFuncAttributeMaxDynamicSharedMemorySize, SMEM_BYTES);

    logic_kernel<<<B_ROWS / ROWS_PER_CTA, THREADS, SMEM_BYTES>>>(x, out);  // 128 CTAs
}